// round 6
// baseline (speedup 1.0000x reference)
#include <cuda_runtime.h>
#include <cstdint>

#define N_NODES 8192
#define F_DIM   256

// Scratch (no cudaMalloc allowed)
__device__ float g_hT[(size_t)F_DIM * N_NODES];    // (neigh_W @ feat^T), tf32-rounded [256][8192]
__device__ float g_agg[(size_t)N_NODES * F_DIM];   // (adj @ h)/deg, tf32-rounded [8192][256]
__device__ float g_feat[(size_t)N_NODES * F_DIM];  // tf32-rounded features [8192][256]

// ---------------------------------------------------------------------------
// helpers
// ---------------------------------------------------------------------------
__device__ __forceinline__ void cp_async16(uint32_t s, const void* g) {
    asm volatile("cp.async.cg.shared.global [%0], [%1], 16;\n" :: "r"(s), "l"(g));
}
__device__ __forceinline__ void cp_commit() { asm volatile("cp.async.commit_group;\n"); }
template <int N> __device__ __forceinline__ void cp_wait() {
    asm volatile("cp.async.wait_group %0;\n" :: "n"(N));
}
__device__ __forceinline__ float rna_tf32(float f) {
    uint32_t r;
    asm("cvt.rna.tf32.f32 %0, %1;\n" : "=r"(r) : "f"(f));
    return __uint_as_float(r);
}
__device__ __forceinline__ void mma_tf32(float* c, const uint32_t* a, const uint32_t* b) {
    asm volatile(
        "mma.sync.aligned.m16n8k8.row.col.f32.tf32.tf32.f32 "
        "{%0,%1,%2,%3}, {%4,%5,%6,%7}, {%8,%9}, {%0,%1,%2,%3};\n"
        : "+f"(c[0]), "+f"(c[1]), "+f"(c[2]), "+f"(c[3])
        : "r"(a[0]), "r"(a[1]), "r"(a[2]), "r"(a[3]), "r"(b[0]), "r"(b[1]));
}
__device__ __forceinline__ void ldsm_x4(uint32_t& r0, uint32_t& r1, uint32_t& r2,
                                        uint32_t& r3, uint32_t a) {
    asm volatile("ldmatrix.sync.aligned.m8n8.x4.shared.b16 {%0,%1,%2,%3}, [%4];\n"
                 : "=r"(r0), "=r"(r1), "=r"(r2), "=r"(r3) : "r"(a));
}

// ---------------------------------------------------------------------------
// Elementwise tf32 rounding copy (features -> g_feat), float4 per thread.
// ---------------------------------------------------------------------------
__global__ void round_copy_kernel(const float* __restrict__ src, float* __restrict__ dst) {
    const size_t i = (size_t)(blockIdx.x * blockDim.x + threadIdx.x) * 4;
    float4 v = *reinterpret_cast<const float4*>(src + i);
    v.x = rna_tf32(v.x); v.y = rna_tf32(v.y);
    v.z = rna_tf32(v.z); v.w = rna_tf32(v.w);
    *reinterpret_cast<float4*>(dst + i) = v;
}

// ---------------------------------------------------------------------------
// tf32 tensor NT GEMM, tile 128x128x32, 256 threads, 8 warps (2x4, 64x32 tiles)
//   C[m][n] = sum_k A[m][k] * B[n][k];  A lda, B ldb, C ldc row-major
//   ROWSUM   : scale C row m by 1/(sum_K A[m][:]) + 1)   (fused degree norm)
//   CONCAT   : A k in [0,256) from A, [256,512) from A2
//   ROUND_OUT: round stored C to tf32 (rna)
// 4-stage cp.async ring, ONE __syncthreads per stage, prefetch issued before
// compute, register double-buffered ldmatrix fragments.
// All dims are exact multiples of tile sizes -> no bounds checks.
// ---------------------------------------------------------------------------
#define A_FLTS 4608              // 128*36
#define STAGE_FLTS (2 * A_FLTS)
#define NSTAGE 4
#define SMEM_BYTES (NSTAGE * STAGE_FLTS * 4)   // 147456

template <bool ROWSUM, bool CONCAT, bool ROUND_OUT>
__global__ __launch_bounds__(256)
void tgemm(const float* __restrict__ A, const float* __restrict__ A2,
           const float* __restrict__ B, float* __restrict__ C,
           int K, int lda, int ldb, int ldc)
{
    extern __shared__ float sm[];
    __shared__ float s_part[256];
    __shared__ float s_inv[128];

    const int tid  = threadIdx.x;
    const int lane = tid & 31;
    const int wid  = tid >> 5;
    const int wm   = wid & 1;     // warp row (2 x 64 rows)
    const int wn   = wid >> 1;    // warp col (4 x 32 cols)
    const int bm   = blockIdx.y * 128;
    const int bn   = blockIdx.x * 128;

    const uint32_t smem_base = (uint32_t)__cvta_generic_to_shared(sm);

    float acc[4][4][4];
    #pragma unroll
    for (int i = 0; i < 4; i++)
        #pragma unroll
        for (int j = 0; j < 4; j++)
            #pragma unroll
            for (int r = 0; r < 4; r++) acc[i][j][r] = 0.0f;

    // per-thread ldmatrix base offsets (k8 = 0), bytes
    uint32_t a_off, b_off;
    {
        const int ar = wm * 64 + (lane & 7) + ((lane >> 3) & 1) * 8;
        const int ak = ((lane >> 4) & 1) * 4;
        a_off = (uint32_t)(ar * 36 + ak) * 4u;
        const int br = wn * 32 + ((lane >> 4) & 1) * 8 + (lane & 7);
        const int bk = ((lane >> 3) & 1) * 4;
        b_off = (uint32_t)(br * 36 + bk) * 4u + A_FLTS * 4u;
    }

    // cp.async loader indices
    const int a_r  = tid >> 3;          // 0..31
    const int a_kv = (tid & 7) * 4;     // 0,4,...,28

    auto fill = [&](int t) {
        const int k0 = t * 32;
        const int s  = t & (NSTAGE - 1);
        const uint32_t sA = smem_base + (uint32_t)(s * STAGE_FLTS) * 4u;
        const uint32_t sB = sA + A_FLTS * 4u;
        const float* Asrc = A;
        int ka = k0;
        if (CONCAT && k0 >= F_DIM) { Asrc = A2; ka = k0 - F_DIM; }
        #pragma unroll
        for (int p = 0; p < 4; p++) {
            const int r = a_r + 32 * p;
            cp_async16(sA + (uint32_t)(r * 36 + a_kv) * 4u,
                       Asrc + (size_t)(bm + r) * lda + ka + a_kv);
        }
        #pragma unroll
        for (int p = 0; p < 4; p++) {
            const int n = a_r + 32 * p;
            cp_async16(sB + (uint32_t)(n * 36 + a_kv) * 4u,
                       B + (size_t)(bn + n) * ldb + k0 + a_kv);
        }
    };

    float row_acc = 0.0f;
    const int T = K >> 5;

    fill(0); cp_commit();
    fill(1); cp_commit();
    fill(2); cp_commit();

    for (int t = 0; t < T; t++) {
        cp_wait<2>();          // fills t, t+1, t+2 pending -> ensure t complete
        __syncthreads();       // data-ready + slot-(t+3)&3 free (last read t-1)

        if (t + 3 < T) fill(t + 3);
        cp_commit();           // one group per iteration (possibly empty)

        const int s = t & (NSTAGE - 1);
        const uint32_t stage_b = smem_base + (uint32_t)(s * STAGE_FLTS) * 4u;
        const uint32_t a_base = stage_b + a_off;
        const uint32_t b_base = stage_b + b_off;

        // register double-buffered fragment pipeline over k8 = 0,8,16,24
        uint32_t af[2][4][4], bf[2][4][2];
        {
            #pragma unroll
            for (int mi = 0; mi < 4; mi++)
                ldsm_x4(af[0][mi][0], af[0][mi][1], af[0][mi][2], af[0][mi][3],
                        a_base + (uint32_t)(mi * 16 * 36) * 4u);
            #pragma unroll
            for (int pi = 0; pi < 2; pi++)
                ldsm_x4(bf[0][2*pi][0], bf[0][2*pi][1], bf[0][2*pi+1][0], bf[0][2*pi+1][1],
                        b_base + (uint32_t)(pi * 16 * 36) * 4u);
        }
        #pragma unroll
        for (int kk = 0; kk < 4; kk++) {
            const int cur = kk & 1;
            const int nxt = cur ^ 1;
            if (kk < 3) {
                const uint32_t kb = (uint32_t)((kk + 1) * 8) * 4u;
                #pragma unroll
                for (int mi = 0; mi < 4; mi++)
                    ldsm_x4(af[nxt][mi][0], af[nxt][mi][1], af[nxt][mi][2], af[nxt][mi][3],
                            a_base + kb + (uint32_t)(mi * 16 * 36) * 4u);
                #pragma unroll
                for (int pi = 0; pi < 2; pi++)
                    ldsm_x4(bf[nxt][2*pi][0], bf[nxt][2*pi][1],
                            bf[nxt][2*pi+1][0], bf[nxt][2*pi+1][1],
                            b_base + kb + (uint32_t)(pi * 16 * 36) * 4u);
            }
            #pragma unroll
            for (int mi = 0; mi < 4; mi++)
                #pragma unroll
                for (int ni = 0; ni < 4; ni++)
                    mma_tf32(acc[mi][ni], af[cur][mi], bf[cur][ni]);
        }

        if (ROWSUM) {
            const float* Ar = sm + s * STAGE_FLTS + (tid >> 1) * 36 + (tid & 1) * 16;
            const int rot = (tid >> 1) & 3;
            float st = 0.0f;
            #pragma unroll
            for (int i = 0; i < 4; i++) {
                const float4 v = *(const float4*)(Ar + (((i + rot) & 3) * 4));
                st += (v.x + v.y) + (v.z + v.w);
            }
            row_acc += st;
        }
        // no trailing barrier: next iteration's barrier provides the ordering
    }

    __syncthreads();
    if (ROWSUM) {
        s_part[tid] = row_acc;
        __syncthreads();
        if (tid < 128)
            s_inv[tid] = 1.0f / (s_part[2 * tid] + s_part[2 * tid + 1] + 1.0f);
        __syncthreads();
    }

    // epilogue
    #pragma unroll
    for (int mi = 0; mi < 4; mi++) {
        const int lr0 = wm * 64 + mi * 16 + (lane >> 2);
        const int r0  = bm + lr0;
        float s0 = 1.0f, s1 = 1.0f;
        if (ROWSUM) { s0 = s_inv[lr0]; s1 = s_inv[lr0 + 8]; }
        #pragma unroll
        for (int ni = 0; ni < 4; ni++) {
            const int c0 = bn + wn * 32 + ni * 8 + 2 * (lane & 3);
            float* p0 = C + (size_t)r0 * ldc + c0;
            float* p1 = C + (size_t)(r0 + 8) * ldc + c0;
            float2 v0 = make_float2(acc[mi][ni][0] * s0, acc[mi][ni][1] * s0);
            float2 v1 = make_float2(acc[mi][ni][2] * s1, acc[mi][ni][3] * s1);
            if (ROUND_OUT) {
                v0.x = rna_tf32(v0.x); v0.y = rna_tf32(v0.y);
                v1.x = rna_tf32(v1.x); v1.y = rna_tf32(v1.y);
            }
            *reinterpret_cast<float2*>(p0) = v0;
            *reinterpret_cast<float2*>(p1) = v1;
        }
    }
}

// ---------------------------------------------------------------------------
extern "C" void kernel_launch(void* const* d_in, const int* in_sizes, int n_in,
                              void* d_out, int out_size)
{
    const float* features = (const float*)d_in[0];  // [8192, 256]
    const float* adj      = (const float*)d_in[1];  // [8192, 8192]
    const float* neigh_W  = (const float*)d_in[2];  // [256, 256]
    const float* lin_W    = (const float*)d_in[3];  // [256, 512]
    float* out = (float*)d_out;                     // [8192, 256]

    float *hT = nullptr, *agg = nullptr, *feat = nullptr;
    cudaGetSymbolAddress((void**)&hT,   g_hT);
    cudaGetSymbolAddress((void**)&agg,  g_agg);
    cudaGetSymbolAddress((void**)&feat, g_feat);

    cudaFuncSetAttribute(tgemm<false, false, true >,
                         cudaFuncAttributeMaxDynamicSharedMemorySize, SMEM_BYTES);
    cudaFuncSetAttribute(tgemm<true,  false, true >,
                         cudaFuncAttributeMaxDynamicSharedMemorySize, SMEM_BYTES);
    cudaFuncSetAttribute(tgemm<false, true,  false>,
                         cudaFuncAttributeMaxDynamicSharedMemorySize, SMEM_BYTES);

    const dim3 blk(256);

    // 0) feat = round_tf32(features)
    round_copy_kernel<<<1024, 512>>>(features, feat);

    // 1) hT = round_tf32(neigh_W @ feat^T)   M=256, N=8192, K=256
    tgemm<false, false, true><<<dim3(64, 2), blk, SMEM_BYTES>>>(
        neigh_W, nullptr, feat, hT, F_DIM, F_DIM, F_DIM, N_NODES);

    // 2) agg = round_tf32((adj @ hT^T) / (rowsum(adj)+1))  M=8192, N=256, K=8192
    tgemm<true, false, true><<<dim3(2, 64), blk, SMEM_BYTES>>>(
        adj, nullptr, hT, agg, N_NODES, N_NODES, N_NODES, F_DIM);

    // 3) out = [feat | agg] @ lin_W^T   M=8192, N=256, K=512 (concat)
    tgemm<false, true, false><<<dim3(2, 64), blk, SMEM_BYTES>>>(
        feat, agg, lin_W, out, 2 * F_DIM, F_DIM, 2 * F_DIM, F_DIM);
}

// round 7
// speedup vs baseline: 1.1237x; 1.1237x over previous
#include <cuda_runtime.h>
#include <cstdint>

#define N_NODES 8192
#define F_DIM   256
#define KSPLIT  4
#define KCHUNK  (N_NODES / KSPLIT)   // 2048

// Scratch (no cudaMalloc allowed)
__device__ float g_hT[(size_t)F_DIM * N_NODES];            // rna(neigh_W @ feat^T) [256][8192]
__device__ float g_agg[(size_t)N_NODES * F_DIM];           // (adj@h)/deg, tf32-rounded
__device__ float g_feat[(size_t)N_NODES * F_DIM];          // tf32-rounded features
__device__ float g_part[(size_t)KSPLIT * N_NODES * F_DIM]; // split-K partials (32MB)
__device__ float g_rowp[(size_t)KSPLIT * N_NODES];         // partial rowsums

// ---------------------------------------------------------------------------
// helpers
// ---------------------------------------------------------------------------
__device__ __forceinline__ void cp_async16(uint32_t s, const void* g) {
    asm volatile("cp.async.cg.shared.global [%0], [%1], 16;\n" :: "r"(s), "l"(g));
}
__device__ __forceinline__ void cp_commit() { asm volatile("cp.async.commit_group;\n"); }
template <int N> __device__ __forceinline__ void cp_wait() {
    asm volatile("cp.async.wait_group %0;\n" :: "n"(N));
}
__device__ __forceinline__ float rna_tf32(float f) {
    uint32_t r;
    asm("cvt.rna.tf32.f32 %0, %1;\n" : "=r"(r) : "f"(f));
    return __uint_as_float(r);
}
__device__ __forceinline__ void mma_tf32(float* c, const uint32_t* a, const uint32_t* b) {
    asm volatile(
        "mma.sync.aligned.m16n8k8.row.col.f32.tf32.tf32.f32 "
        "{%0,%1,%2,%3}, {%4,%5,%6,%7}, {%8,%9}, {%0,%1,%2,%3};\n"
        : "+f"(c[0]), "+f"(c[1]), "+f"(c[2]), "+f"(c[3])
        : "r"(a[0]), "r"(a[1]), "r"(a[2]), "r"(a[3]), "r"(b[0]), "r"(b[1]));
}
__device__ __forceinline__ void ldsm_x4(uint32_t& r0, uint32_t& r1, uint32_t& r2,
                                        uint32_t& r3, uint32_t a) {
    asm volatile("ldmatrix.sync.aligned.m8n8.x4.shared.b16 {%0,%1,%2,%3}, [%4];\n"
                 : "=r"(r0), "=r"(r1), "=r"(r2), "=r"(r3) : "r"(a));
}

// ---------------------------------------------------------------------------
// Elementwise tf32 rounding copy (features -> g_feat)
// ---------------------------------------------------------------------------
__global__ void round_copy_kernel(const float* __restrict__ src, float* __restrict__ dst) {
    const size_t i = (size_t)(blockIdx.x * blockDim.x + threadIdx.x) * 4;
    float4 v = *reinterpret_cast<const float4*>(src + i);
    v.x = rna_tf32(v.x); v.y = rna_tf32(v.y);
    v.z = rna_tf32(v.z); v.w = rna_tf32(v.w);
    *reinterpret_cast<float4*>(dst + i) = v;
}

// ---------------------------------------------------------------------------
// Reduce for the big GEMM: agg = rna( (sum_s part[s]) / (sum_s rowp[s] + 1) )
// ---------------------------------------------------------------------------
__global__ void reduce_big_kernel(const float* __restrict__ part,
                                  const float* __restrict__ rowp,
                                  float* __restrict__ agg) {
    const size_t i = (size_t)(blockIdx.x * blockDim.x + threadIdx.x) * 4;
    const int row = (int)(i >> 8);   // / F_DIM
    const float inv = 1.0f / (rowp[row] + rowp[N_NODES + row] +
                              rowp[2 * N_NODES + row] + rowp[3 * N_NODES + row] + 1.0f);
    const size_t MN = (size_t)N_NODES * F_DIM;
    float4 a = *reinterpret_cast<const float4*>(part + i);
    float4 b = *reinterpret_cast<const float4*>(part + MN + i);
    float4 c = *reinterpret_cast<const float4*>(part + 2 * MN + i);
    float4 d = *reinterpret_cast<const float4*>(part + 3 * MN + i);
    float4 o;
    o.x = rna_tf32((a.x + b.x + c.x + d.x) * inv);
    o.y = rna_tf32((a.y + b.y + c.y + d.y) * inv);
    o.z = rna_tf32((a.z + b.z + c.z + d.z) * inv);
    o.w = rna_tf32((a.w + b.w + c.w + d.w) * inv);
    *reinterpret_cast<float4*>(agg + i) = o;
}

// ---------------------------------------------------------------------------
// Reduce for the output GEMM: out = part[0] + part[1]
// ---------------------------------------------------------------------------
__global__ void reduce_out_kernel(const float* __restrict__ part, float* __restrict__ out) {
    const size_t i = (size_t)(blockIdx.x * blockDim.x + threadIdx.x) * 4;
    const size_t MN = (size_t)N_NODES * F_DIM;
    float4 a = *reinterpret_cast<const float4*>(part + i);
    float4 b = *reinterpret_cast<const float4*>(part + MN + i);
    float4 o = make_float4(a.x + b.x, a.y + b.y, a.z + b.z, a.w + b.w);
    *reinterpret_cast<float4*>(out + i) = o;
}

// ---------------------------------------------------------------------------
// tf32 tensor NT GEMM, tile 128x128x32, 256 threads, 8 warps (2x4, 64x32 tiles)
//   C[m][n] = sum_k A[m][k] * B[n][k] over K columns starting at the split
//   offset. blockIdx.z = split index zz:
//     B k-offset = zz*K always; A k-offset = zz*K unless CONCAT.
//     CONCAT: split 0 reads A, split 1 reads A2 (k-offset 0) -> concat GEMM.
//     C += zz * c_split_stride.
//   ROWSUM   : store partial rowsum(A-chunk) to rowp (bn==0 CTAs), no scaling.
//   ROUND_OUT: round stored C to tf32.
// 3-stage cp.async ring, one barrier/stage, 2 CTAs/SM.
// ---------------------------------------------------------------------------
#define A_FLTS 4608              // 128*36
#define STAGE_FLTS (2 * A_FLTS)
#define NSTAGE 3
#define SMEM_BYTES (NSTAGE * STAGE_FLTS * 4)   // 110592

template <bool ROWSUM, bool CONCAT, bool ROUND_OUT>
__global__ __launch_bounds__(256, 2)
void tgemm(const float* __restrict__ A, const float* __restrict__ A2,
           const float* __restrict__ B, float* __restrict__ C,
           float* __restrict__ rowp,
           int K, int lda, int ldb, int ldc, size_t c_split_stride)
{
    extern __shared__ float sm[];
    __shared__ float s_part[256];

    const int tid  = threadIdx.x;
    const int lane = tid & 31;
    const int wid  = tid >> 5;
    const int wm   = wid & 1;
    const int wn   = wid >> 1;
    const int bm   = blockIdx.y * 128;
    const int bn   = blockIdx.x * 128;
    const int zz   = blockIdx.z;

    C += (size_t)zz * c_split_stride;
    const int koffB = zz * K;
    const int koffA = CONCAT ? 0 : koffB;
    const float* Abase = (CONCAT && zz) ? A2 : A;

    const uint32_t smem_base = (uint32_t)__cvta_generic_to_shared(sm);

    float acc[4][4][4];
    #pragma unroll
    for (int i = 0; i < 4; i++)
        #pragma unroll
        for (int j = 0; j < 4; j++)
            #pragma unroll
            for (int r = 0; r < 4; r++) acc[i][j][r] = 0.0f;

    // per-thread ldmatrix base offsets (k8 = 0), bytes
    uint32_t a_off, b_off;
    {
        const int ar = wm * 64 + (lane & 7) + ((lane >> 3) & 1) * 8;
        const int ak = ((lane >> 4) & 1) * 4;
        a_off = (uint32_t)(ar * 36 + ak) * 4u;
        const int br = wn * 32 + ((lane >> 4) & 1) * 8 + (lane & 7);
        const int bk = ((lane >> 3) & 1) * 4;
        b_off = (uint32_t)(br * 36 + bk) * 4u + A_FLTS * 4u;
    }

    // cp.async loader indices
    const int a_r  = tid >> 3;          // 0..31
    const int a_kv = (tid & 7) * 4;     // 0,4,...,28

    auto fill = [&](int t) {
        const int k0 = t * 32;
        const int s  = t % NSTAGE;
        const uint32_t sA = smem_base + (uint32_t)(s * STAGE_FLTS) * 4u;
        const uint32_t sB = sA + A_FLTS * 4u;
        #pragma unroll
        for (int p = 0; p < 4; p++) {
            const int r = a_r + 32 * p;
            cp_async16(sA + (uint32_t)(r * 36 + a_kv) * 4u,
                       Abase + (size_t)(bm + r) * lda + koffA + k0 + a_kv);
        }
        #pragma unroll
        for (int p = 0; p < 4; p++) {
            const int n = a_r + 32 * p;
            cp_async16(sB + (uint32_t)(n * 36 + a_kv) * 4u,
                       B + (size_t)(bn + n) * ldb + koffB + k0 + a_kv);
        }
    };

    float row_acc = 0.0f;
    const int T = K >> 5;

    fill(0); cp_commit();
    fill(1); cp_commit();

    for (int t = 0; t < T; t++) {
        cp_wait<1>();
        __syncthreads();

        if (t + 2 < T) fill(t + 2);
        cp_commit();

        const int s = t % NSTAGE;
        const uint32_t stage_b = smem_base + (uint32_t)(s * STAGE_FLTS) * 4u;
        const uint32_t a_base = stage_b + a_off;
        const uint32_t b_base = stage_b + b_off;

        #pragma unroll
        for (int k8 = 0; k8 < 32; k8 += 8) {
            const uint32_t kb = (uint32_t)k8 * 4u;
            uint32_t af[4][4];
            #pragma unroll
            for (int mi = 0; mi < 4; mi++)
                ldsm_x4(af[mi][0], af[mi][1], af[mi][2], af[mi][3],
                        a_base + kb + (uint32_t)(mi * 16 * 36) * 4u);
            uint32_t bf[4][2];
            #pragma unroll
            for (int pi = 0; pi < 2; pi++)
                ldsm_x4(bf[2 * pi][0], bf[2 * pi][1], bf[2 * pi + 1][0], bf[2 * pi + 1][1],
                        b_base + kb + (uint32_t)(pi * 16 * 36) * 4u);
            #pragma unroll
            for (int mi = 0; mi < 4; mi++)
                #pragma unroll
                for (int ni = 0; ni < 4; ni++)
                    mma_tf32(acc[mi][ni], af[mi], bf[ni]);
        }

        if (ROWSUM) {
            const float* Ar = sm + s * STAGE_FLTS + (tid >> 1) * 36 + (tid & 1) * 16;
            const int rot = (tid >> 1) & 3;
            float st = 0.0f;
            #pragma unroll
            for (int i = 0; i < 4; i++) {
                const float4 v = *(const float4*)(Ar + (((i + rot) & 3) * 4));
                st += (v.x + v.y) + (v.z + v.w);
            }
            row_acc += st;
        }
    }

    __syncthreads();
    if (ROWSUM) {
        s_part[tid] = row_acc;
        __syncthreads();
        if (tid < 128 && blockIdx.x == 0)
            rowp[(size_t)zz * (gridDim.y * 128) + bm + tid] =
                s_part[2 * tid] + s_part[2 * tid + 1];
    }

    // epilogue (raw partials for split mode; optional tf32 rounding)
    #pragma unroll
    for (int mi = 0; mi < 4; mi++) {
        const int r0 = bm + wm * 64 + mi * 16 + (lane >> 2);
        #pragma unroll
        for (int ni = 0; ni < 4; ni++) {
            const int c0 = bn + wn * 32 + ni * 8 + 2 * (lane & 3);
            float* p0 = C + (size_t)r0 * ldc + c0;
            float* p1 = C + (size_t)(r0 + 8) * ldc + c0;
            float2 v0 = make_float2(acc[mi][ni][0], acc[mi][ni][1]);
            float2 v1 = make_float2(acc[mi][ni][2], acc[mi][ni][3]);
            if (ROUND_OUT) {
                v0.x = rna_tf32(v0.x); v0.y = rna_tf32(v0.y);
                v1.x = rna_tf32(v1.x); v1.y = rna_tf32(v1.y);
            }
            *reinterpret_cast<float2*>(p0) = v0;
            *reinterpret_cast<float2*>(p1) = v1;
        }
    }
}

// ---------------------------------------------------------------------------
extern "C" void kernel_launch(void* const* d_in, const int* in_sizes, int n_in,
                              void* d_out, int out_size)
{
    const float* features = (const float*)d_in[0];  // [8192, 256]
    const float* adj      = (const float*)d_in[1];  // [8192, 8192]
    const float* neigh_W  = (const float*)d_in[2];  // [256, 256]
    const float* lin_W    = (const float*)d_in[3];  // [256, 512]
    float* out = (float*)d_out;                     // [8192, 256]

    float *hT, *agg, *feat, *part, *rowp;
    cudaGetSymbolAddress((void**)&hT,   g_hT);
    cudaGetSymbolAddress((void**)&agg,  g_agg);
    cudaGetSymbolAddress((void**)&feat, g_feat);
    cudaGetSymbolAddress((void**)&part, g_part);
    cudaGetSymbolAddress((void**)&rowp, g_rowp);

    cudaFuncSetAttribute(tgemm<false, false, true >,
                         cudaFuncAttributeMaxDynamicSharedMemorySize, SMEM_BYTES);
    cudaFuncSetAttribute(tgemm<true,  false, false>,
                         cudaFuncAttributeMaxDynamicSharedMemorySize, SMEM_BYTES);
    cudaFuncSetAttribute(tgemm<false, true,  false>,
                         cudaFuncAttributeMaxDynamicSharedMemorySize, SMEM_BYTES);

    const dim3 blk(256);
    const size_t MN = (size_t)N_NODES * F_DIM;

    // 0) feat = round_tf32(features)
    round_copy_kernel<<<1024, 512>>>(features, feat);

    // 1) hT = rna(neigh_W @ feat^T)   M=256, N=8192, K=256
    tgemm<false, false, true><<<dim3(64, 2, 1), blk, SMEM_BYTES>>>(
        neigh_W, nullptr, feat, hT, nullptr,
        F_DIM, F_DIM, F_DIM, N_NODES, 0);

    // 2) split-K x4 partials of adj @ hT^T (+ partial rowsums)
    //    M=8192, N=256, K=2048/split; grid (2, 64, 4) = 512 CTAs
    tgemm<true, false, false><<<dim3(2, 64, KSPLIT), blk, SMEM_BYTES>>>(
        adj, nullptr, hT, part, rowp,
        KCHUNK, N_NODES, N_NODES, F_DIM, MN);

    // 2b) agg = rna( (sum parts) / (sum rowsums + 1) )
    reduce_big_kernel<<<2048, 256>>>(part, rowp, agg);

    // 3) split concat GEMM: z=0: feat @ lin_W[:, :256]^T; z=1: agg @ lin_W[:, 256:]^T
    tgemm<false, true, false><<<dim3(2, 64, 2), blk, SMEM_BYTES>>>(
        feat, agg, lin_W, part, nullptr,
        F_DIM, F_DIM, 2 * F_DIM, F_DIM, MN);

    // 3b) out = part0 + part1
    reduce_out_kernel<<<2048, 256>>>(part, out);
}